// round 4
// baseline (speedup 1.0000x reference)
#include <cuda_runtime.h>
#include <cuda_fp16.h>
#include <cstddef>
#include <cstdint>

#define VOCAB 100000
#define NB    16384
#define LSEQ  200
#define EMB   128
#define NCLS  1000

// Scratch (alloc-free rule: __device__ globals).
__device__ __half g_table_h[(size_t)VOCAB * EMB];   // 25.6 MB fp16 table
__device__ __half g_w_h[(size_t)NCLS * EMB];        // 256 KB fp16 weights
__device__ __half g_pooled_h[(size_t)NB * EMB];     // 4 MB pooled (fp16)

// ---------------------------------------------------------------------------
// Stage 0: convert table AND fc_w fp32 -> fp16. 4 independent float4 per
// thread (MLP_p1 = 4) to cover DRAM latency in this streaming kernel.
// ---------------------------------------------------------------------------
#define N_TBL4 ((size_t)VOCAB * EMB / 4)   // 3,200,000 float4
#define N_W4   ((size_t)NCLS * EMB / 4)    //    32,000 float4
#define N_ALL4 (N_TBL4 + N_W4)             // 3,232,000

__global__ __launch_bounds__(256) void convert_kernel(const float* __restrict__ t,
                                                      const float* __restrict__ W) {
    const size_t base = (size_t)blockIdx.x * 1024 + threadIdx.x;
    float4 v[4];
    bool   ok[4];
    #pragma unroll
    for (int i = 0; i < 4; ++i) {
        const size_t idx = base + (size_t)i * 256;
        ok[i] = idx < N_ALL4;
        if (ok[i])
            v[i] = (idx < N_TBL4) ? reinterpret_cast<const float4*>(t)[idx]
                                  : reinterpret_cast<const float4*>(W)[idx - N_TBL4];
    }
    #pragma unroll
    for (int i = 0; i < 4; ++i) {
        if (!ok[i]) continue;
        const size_t idx = base + (size_t)i * 256;
        union { __half2 h[2]; uint2 u; } pk;
        pk.h[0] = __floats2half2_rn(v[i].x, v[i].y);
        pk.h[1] = __floats2half2_rn(v[i].z, v[i].w);
        if (idx < N_TBL4) reinterpret_cast<uint2*>(g_table_h)[idx] = pk.u;
        else              reinterpret_cast<uint2*>(g_w_h)[idx - N_TBL4] = pk.u;
    }
}

// ---------------------------------------------------------------------------
// Stage 1: masked embedding-bag sum pool (fp16 gathers, fp32 acc, fp16 out).
// One warp per batch row; lane owns 4 dims (uint2 = half4 loads).
// 8 outstanding gathers per iteration; .cg loads bypass L1 (hit rate ~0.9%,
// allocation is pure overhead).
// ---------------------------------------------------------------------------
__device__ __forceinline__ void hacc(float4& a, uint2 u) {
    const float2 f0 = __half22float2(*reinterpret_cast<__half2*>(&u.x));
    const float2 f1 = __half22float2(*reinterpret_cast<__half2*>(&u.y));
    a.x += f0.x; a.y += f0.y; a.z += f1.x; a.w += f1.y;
}

__global__ __launch_bounds__(256) void pool_kernel(const int* __restrict__ seq) {
    __shared__ int s_tok[8][LSEQ];
    const int wid  = threadIdx.x >> 5;
    const int lane = threadIdx.x & 31;
    const int b0   = blockIdx.x * 8;

    for (int i = threadIdx.x; i < 8 * LSEQ; i += 256)
        s_tok[i / LSEQ][i % LSEQ] = seq[(size_t)b0 * LSEQ + i];
    __syncthreads();

    float4 acc[8];
    #pragma unroll
    for (int i = 0; i < 8; ++i) acc[i] = make_float4(0.f, 0.f, 0.f, 0.f);

    for (int l = 0; l < LSEQ; l += 8) {   // 200 % 8 == 0
        int  tok[8];
        uint2 v[8];
        #pragma unroll
        for (int i = 0; i < 8; ++i) tok[i] = s_tok[wid][l + i];
        #pragma unroll
        for (int i = 0; i < 8; ++i)
            if (tok[i])
                v[i] = __ldcg(reinterpret_cast<const uint2*>(
                           g_table_h + (size_t)tok[i] * EMB) + lane);
        #pragma unroll
        for (int i = 0; i < 8; ++i)
            if (tok[i]) hacc(acc[i], v[i]);
    }

    float4 r;
    r.x = ((acc[0].x + acc[1].x) + (acc[2].x + acc[3].x)) +
          ((acc[4].x + acc[5].x) + (acc[6].x + acc[7].x));
    r.y = ((acc[0].y + acc[1].y) + (acc[2].y + acc[3].y)) +
          ((acc[4].y + acc[5].y) + (acc[6].y + acc[7].y));
    r.z = ((acc[0].z + acc[1].z) + (acc[2].z + acc[3].z)) +
          ((acc[4].z + acc[5].z) + (acc[6].z + acc[7].z));
    r.w = ((acc[0].w + acc[1].w) + (acc[2].w + acc[3].w)) +
          ((acc[4].w + acc[5].w) + (acc[6].w + acc[7].w));

    union { __half2 h[2]; uint2 u; } pk;
    pk.h[0] = __floats2half2_rn(r.x, r.y);
    pk.h[1] = __floats2half2_rn(r.z, r.w);
    reinterpret_cast<uint2*>(g_pooled_h + (size_t)(b0 + wid) * EMB)[lane] = pk.u;
}

// ---------------------------------------------------------------------------
// Stage 2: HMMA GEMM. out[m,n] = pooled[m,:] . W[n,:] + bias[n]
// Block tile 128(m) x 128(n), K=128 resident in smem (64 KB, XOR swizzle).
// 8 warps as 2(m) x 4(n); warp tile 64x32 via 4x4 mma.m16n8k16, 8 k-steps.
// ---------------------------------------------------------------------------
__device__ __forceinline__ void mma16816(float* d,
                                         uint32_t a0, uint32_t a1, uint32_t a2, uint32_t a3,
                                         uint32_t b0, uint32_t b1) {
    asm volatile(
        "mma.sync.aligned.m16n8k16.row.col.f32.f16.f16.f32 "
        "{%0,%1,%2,%3}, {%4,%5,%6,%7}, {%8,%9}, {%0,%1,%2,%3};\n"
        : "+f"(d[0]), "+f"(d[1]), "+f"(d[2]), "+f"(d[3])
        : "r"(a0), "r"(a1), "r"(a2), "r"(a3), "r"(b0), "r"(b1));
}

// smem half-index with 16B-chunk XOR swizzle: row has 16 chunks of 8 halfs;
// data chunk c of row r lives at chunk (c ^ (r&7)).
__device__ __forceinline__ int swz(int row, int chunk) {
    return row * 128 + ((chunk ^ (row & 7)) << 3);
}

__global__ __launch_bounds__(256) void gemm_kernel(const float* __restrict__ bias,
                                                   float* __restrict__ out) {
    __shared__ __half sA[128 * 128];   // 32 KB
    __shared__ __half sB[128 * 128];   // 32 KB

    const int tid  = threadIdx.x;
    const int lane = tid & 31;
    const int wid  = tid >> 5;
    const int wm   = wid >> 2;         // 0..1 (m)
    const int wn   = wid & 3;          // 0..3 (n)
    const int m0   = blockIdx.x * 128;
    const int n0   = blockIdx.y * 128;

    // --- load A tile: 128 rows x 16 chunks(16B), fully coalesced ---
    {
        const int r0 = tid >> 4;          // 0..15
        const int c  = tid & 15;          // chunk
        #pragma unroll
        for (int it = 0; it < 8; ++it) {
            const int r = r0 + it * 16;
            const uint4 v = reinterpret_cast<const uint4*>(
                g_pooled_h + (size_t)(m0 + r) * EMB)[c];
            *reinterpret_cast<uint4*>(&sA[swz(r, c)]) = v;
        }
    }
    // --- load B tile: 128 rows x 16 chunks, rows >= NCLS zero-filled ---
    {
        const int r0 = tid >> 4;
        const int c  = tid & 15;
        #pragma unroll
        for (int it = 0; it < 8; ++it) {
            const int r = r0 + it * 16;
            uint4 v = make_uint4(0u, 0u, 0u, 0u);
            if (n0 + r < NCLS)
                v = reinterpret_cast<const uint4*>(g_w_h + (size_t)(n0 + r) * EMB)[c];
            *reinterpret_cast<uint4*>(&sB[swz(r, c)]) = v;
        }
    }
    __syncthreads();

    float acc[4][4][4] = {};
    const int lq = lane >> 2;   // 0..7
    const int lr = lane & 3;    // 0..3

    #pragma unroll
    for (int ks = 0; ks < 8; ++ks) {
        uint32_t a[4][4];
        #pragma unroll
        for (int mt = 0; mt < 4; ++mt) {
            const int r   = wm * 64 + mt * 16 + lq;
            const int o0  = ((2 * ks)     ^ (r & 7)) * 8 + lr * 2;
            const int o1  = ((2 * ks + 1) ^ (r & 7)) * 8 + lr * 2;
            a[mt][0] = *reinterpret_cast<const uint32_t*>(&sA[r * 128 + o0]);
            a[mt][1] = *reinterpret_cast<const uint32_t*>(&sA[(r + 8) * 128 + o0]);
            a[mt][2] = *reinterpret_cast<const uint32_t*>(&sA[r * 128 + o1]);
            a[mt][3] = *reinterpret_cast<const uint32_t*>(&sA[(r + 8) * 128 + o1]);
        }
        #pragma unroll
        for (int nt = 0; nt < 4; ++nt) {
            const int n  = wn * 32 + nt * 8 + lq;
            const int o0 = ((2 * ks)     ^ (n & 7)) * 8 + lr * 2;
            const int o1 = ((2 * ks + 1) ^ (n & 7)) * 8 + lr * 2;
            const uint32_t b0 = *reinterpret_cast<const uint32_t*>(&sB[n * 128 + o0]);
            const uint32_t b1 = *reinterpret_cast<const uint32_t*>(&sB[n * 128 + o1]);
            #pragma unroll
            for (int mt = 0; mt < 4; ++mt)
                mma16816(acc[mt][nt], a[mt][0], a[mt][1], a[mt][2], a[mt][3], b0, b1);
        }
    }

    // --- epilogue: fused bias, predicated float2 stores ---
    #pragma unroll
    for (int nt = 0; nt < 4; ++nt) {
        const int n = n0 + wn * 32 + nt * 8 + lr * 2;   // even
        if (n < NCLS) {
            const float2 b2 = *reinterpret_cast<const float2*>(bias + n);
            #pragma unroll
            for (int mt = 0; mt < 4; ++mt) {
                const int m = m0 + wm * 64 + mt * 16 + lq;
                float2 r0, r1;
                r0.x = acc[mt][nt][0] + b2.x;
                r0.y = acc[mt][nt][1] + b2.y;
                r1.x = acc[mt][nt][2] + b2.x;
                r1.y = acc[mt][nt][3] + b2.y;
                *reinterpret_cast<float2*>(out + (size_t)m * NCLS + n)       = r0;
                *reinterpret_cast<float2*>(out + (size_t)(m + 8) * NCLS + n) = r1;
            }
        }
    }
}

extern "C" void kernel_launch(void* const* d_in, const int* in_sizes, int n_in,
                              void* d_out, int out_size) {
    const int*   seq   = (const int*)d_in[0];
    const float* table = (const float*)d_in[1];
    const float* W     = (const float*)d_in[2];
    const float* bias  = (const float*)d_in[3];
    float*       out   = (float*)d_out;

    const int conv_blocks = (int)((N_ALL4 + 1023) / 1024);
    convert_kernel<<<conv_blocks, 256>>>(table, W);

    pool_kernel<<<NB / 8, 256>>>(seq);

    dim3 grid(NB / 128, (NCLS + 127) / 128);
    gemm_kernel<<<grid, 256>>>(bias, out);
}